// round 17
// baseline (speedup 1.0000x reference)
#include <cuda_runtime.h>
#include <cuda_fp16.h>
#include <cstdint>

// out[65536,64] = A[65536,512] @ B[512,64], A[b, c*64 + s*16 + half*8 + F] =
// prim_{2s+half}(x[b, 8c+F]).  K-reordered so each thread computes its own mma
// A-fragments in registers (no staging, no mainloop barriers).
// m16n64 warp tile, 128 rows/CTA, grid 512, 3 CTAs/SM for occupancy.

#define NW 16384                     // W words: [c8][s4][fp4][lane32][4] = 64 KB
__device__ uint32_t g_W[NW];

static __device__ __forceinline__ uint32_t pk(float lo, float hi) {
    __half2 h = __floats2half2_rn(lo, hi);
    return *reinterpret_cast<uint32_t*>(&h);
}

static __device__ __forceinline__ void mma16(float c[4], uint32_t a0, uint32_t a1,
                                             uint32_t a2, uint32_t a3,
                                             uint32_t b0, uint32_t b1) {
    asm volatile(
        "mma.sync.aligned.m16n8k16.row.col.f32.f16.f16.f32 "
        "{%0,%1,%2,%3}, {%4,%5,%6,%7}, {%8,%9}, {%0,%1,%2,%3};"
        : "+f"(c[0]), "+f"(c[1]), "+f"(c[2]), "+f"(c[3])
        : "r"(a0), "r"(a1), "r"(a2), "r"(a3), "r"(b0), "r"(b1));
}
static __device__ __forceinline__ void mma8(float c[4], uint32_t a0, uint32_t a1,
                                            uint32_t b0) {
    asm volatile(
        "mma.sync.aligned.m16n8k8.row.col.f32.f16.f16.f32 "
        "{%0,%1,%2,%3}, {%4,%5}, {%6}, {%0,%1,%2,%3};"
        : "+f"(c[0]), "+f"(c[1]), "+f"(c[2]), "+f"(c[3])
        : "r"(a0), "r"(a1), "r"(b0));
}

// ---------------------------------------------------------------------------
// prep: build W into fragment layout (verified R15). 2048 threads.
// ---------------------------------------------------------------------------
__global__ void prep_w(const float* __restrict__ alphas,
                       const float* __restrict__ coeffs) {
    int id = blockIdx.x * blockDim.x + threadIdx.x;   // 0..2047
    int ip = id >> 6, j = id & 63;
    float w[2][8];
#pragma unroll
    for (int e = 0; e < 2; ++e) {
        int i = ip * 2 + e;
        const float4* av = (const float4*)(alphas + ((size_t)i * 64 + j) * 8);
        const float4* cv = (const float4*)(coeffs + ((size_t)i * 64 + j) * 8);
        float4 a0 = av[0], a1 = av[1], c0 = cv[0], c1 = cv[1];
        float e0 = __expf(a0.x), e1 = __expf(a0.y), e2 = __expf(a0.z), e3 = __expf(a0.w);
        float e4 = __expf(a1.x), e5 = __expf(a1.y), e6 = __expf(a1.z), e7 = __expf(a1.w);
        float inv = 1.0f / (e0 + e1 + e2 + e3 + e4 + e5 + e6 + e7);
        w[e][0] = 0.0f;            w[e][1] = e1 * inv * c0.y;
        w[e][2] = e2 * inv * c0.z; w[e][3] = e3 * inv * c0.w;
        w[e][4] = e4 * inv * c1.x; w[e][5] = e5 * inv * c1.y;
        w[e][6] = e6 * inv * c1.z; w[e][7] = e7 * inv * c1.w;
    }
    int c = ip >> 2, q = ip & 3;
    int lane = (j & 7) * 4 + q, fb = j >> 3;
#pragma unroll
    for (int o = 0; o < 8; ++o) {
        int s = o >> 1, slot = o & 1;
        g_W[(((c * 4 + s) * 4 + (fb >> 1)) * 32 + lane) * 4 + (fb & 1) * 2 + slot] =
            pk(w[0][o], w[1][o]);
    }
}

// ---------------------------------------------------------------------------
// main: 512 CTAs x 256 threads (8 warps, m16n64 each), 3 CTAs/SM.
// ---------------------------------------------------------------------------
__global__ void __launch_bounds__(256, 3)
darts_kernel(const float* __restrict__ x, float* __restrict__ out) {
    extern __shared__ uint32_t sW[];
    int tid = threadIdx.x, lane = tid & 31, warp = tid >> 5;
    int qrow = lane >> 2, qcol = lane & 3;

    // copy W (64 KB) global -> shared, coalesced
    {
        const uint4* g4 = (const uint4*)g_W;
        uint4* s4 = (uint4*)sW;
#pragma unroll
        for (int k = 0; k < 16; ++k) s4[tid + k * 256] = g4[tid + k * 256];
    }
    __syncthreads();

    float acc[8][4];
#pragma unroll
    for (int f = 0; f < 8; ++f)
#pragma unroll
        for (int q = 0; q < 4; ++q) acc[f][q] = 0.f;

    // thread's 2 rows: qrow, qrow+8 within warp's 16-row tile; features 2qcol,2qcol+1
    size_t grow = (size_t)blockIdx.x * 128 + warp * 16 + qrow;
    const float* px = x + grow * 64 + 2 * qcol;

    float2 xc0 = *(const float2*)px;             // row qrow
    float2 xc1 = *(const float2*)(px + 512);     // row qrow+8

#pragma unroll 2
    for (int c = 0; c < 8; ++c) {
        float2 xn0 = xc0, xn1 = xc1;
        if (c < 7) {
            xn0 = *(const float2*)(px + (c + 1) * 8);
            xn1 = *(const float2*)(px + 512 + (c + 1) * 8);
        }
        const uint4* wb = (const uint4*)sW + (c * 16) * 32 + lane;
        uint32_t A0a, A0b, A1a, A1b;

        // ---- s=0: (none, linear) -> k8 mma on high half only
        A1a = pk(xc0.x, xc0.y);
        A1b = pk(xc1.x, xc1.y);
#pragma unroll
        for (int fp = 0; fp < 4; ++fp) {
            uint4 B = wb[fp * 32];
            mma8(acc[2 * fp],     A1a, A1b, B.y);
            mma8(acc[2 * fp + 1], A1a, A1b, B.w);
        }
        // ---- s=1: (x^2, x^3)
        {
            float a2 = xc0.x * xc0.x, b2 = xc0.y * xc0.y;
            float c2 = xc1.x * xc1.x, d2 = xc1.y * xc1.y;
            A0a = pk(a2, b2);            A0b = pk(c2, d2);
            A1a = pk(a2 * xc0.x, b2 * xc0.y);
            A1b = pk(c2 * xc1.x, d2 * xc1.y);
        }
#pragma unroll
        for (int fp = 0; fp < 4; ++fp) {
            uint4 B = wb[(4 + fp) * 32];
            mma16(acc[2 * fp],     A0a, A0b, A1a, A1b, B.x, B.y);   // FIX: a1<->a2 order
            mma16(acc[2 * fp + 1], A0a, A0b, A1a, A1b, B.z, B.w);
        }
        // ---- s=2: (exp, ln)
        A0a = pk(__expf(xc0.x), __expf(xc0.y));
        A0b = pk(__expf(xc1.x), __expf(xc1.y));
        A1a = pk(__logf(xc0.x), __logf(xc0.y));
        A1b = pk(__logf(xc1.x), __logf(xc1.y));
#pragma unroll
        for (int fp = 0; fp < 4; ++fp) {
            uint4 B = wb[(8 + fp) * 32];
            mma16(acc[2 * fp],     A0a, A0b, A1a, A1b, B.x, B.y);
            mma16(acc[2 * fp + 1], A0a, A0b, A1a, A1b, B.z, B.w);
        }
        // ---- s=3: (1/x, sin)
        {
            float r0, r1, r2, r3;
            asm("rcp.approx.f32 %0, %1;" : "=f"(r0) : "f"(xc0.x));
            asm("rcp.approx.f32 %0, %1;" : "=f"(r1) : "f"(xc0.y));
            asm("rcp.approx.f32 %0, %1;" : "=f"(r2) : "f"(xc1.x));
            asm("rcp.approx.f32 %0, %1;" : "=f"(r3) : "f"(xc1.y));
            A0a = pk(r0, r1);  A0b = pk(r2, r3);
        }
        A1a = pk(__sinf(xc0.x), __sinf(xc0.y));
        A1b = pk(__sinf(xc1.x), __sinf(xc1.y));
#pragma unroll
        for (int fp = 0; fp < 4; ++fp) {
            uint4 B = wb[(12 + fp) * 32];
            mma16(acc[2 * fp],     A0a, A0b, A1a, A1b, B.x, B.y);
            mma16(acc[2 * fp + 1], A0a, A0b, A1a, A1b, B.z, B.w);
        }
        xc0 = xn0;
        xc1 = xn1;
    }

    // ---- epilogue: rows qrow (c0,c1), qrow+8 (c2,c3)
    size_t r = (size_t)blockIdx.x * 128 + warp * 16 + qrow;
#pragma unroll
    for (int f = 0; f < 8; ++f) {
        int col = f * 8 + qcol * 2;
        *(float2*)(out + r * 64 + col)       = make_float2(acc[f][0], acc[f][1]);
        *(float2*)(out + (r + 8) * 64 + col) = make_float2(acc[f][2], acc[f][3]);
    }
}

extern "C" void kernel_launch(void* const* d_in, const int* in_sizes, int n_in,
                              void* d_out, int out_size) {
    const float* x      = (const float*)d_in[0];   // [65536, 64]
    const float* alphas = (const float*)d_in[1];   // [64, 64, 8]
    const float* coeffs = (const float*)d_in[2];   // [64, 64, 8]
    cudaFuncSetAttribute((const void*)darts_kernel,
                         cudaFuncAttributeMaxDynamicSharedMemorySize, 65536);
    prep_w<<<8, 256>>>(alphas, coeffs);
    darts_kernel<<<512, 256, 65536>>>(x, (float*)d_out);
}